// round 6
// baseline (speedup 1.0000x reference)
#include <cuda_runtime.h>
#include <cuda_bf16.h>
#include <cstdint>

#define Bsz 8
#define FD 1024
#define NN 65536
#define BNN (Bsz*NN)
#define Ksel 39321
#define M_TOT 2048

// ---------------- scratch ----------------
__device__ float    g_pp[M_TOT * 512];
__device__ float    g_e[BNN];
__device__ unsigned g_maxkey[Bsz];
__device__ float    g_inv_denom[Bsz];
__device__ float    g_part[Bsz * 64];
__device__ float    g_thr[Bsz];
__device__ float    g_cpart[Bsz * 64];
__device__ float    g_inv_csum[Bsz];

// bf16 triple-split operands (x and W in Bmat[j][f] layout)
__device__ __nv_bfloat16 g_xh[M_TOT * FD];
__device__ __nv_bfloat16 g_xm[M_TOT * FD];
__device__ __nv_bfloat16 g_xl[M_TOT * FD];
__device__ __nv_bfloat16 g_wh[512 * FD];
__device__ __nv_bfloat16 g_wm[512 * FD];
__device__ __nv_bfloat16 g_wl[512 * FD];

// monotone float<->uint encoding
__device__ __forceinline__ unsigned encf(float f) {
    unsigned u = __float_as_uint(f);
    return (u & 0x80000000u) ? ~u : (u | 0x80000000u);
}
__device__ __forceinline__ float decf(unsigned u) {
    unsigned v = (u & 0x80000000u) ? (u ^ 0x80000000u) : ~u;
    return __uint_as_float(v);
}

__global__ void init_kernel() {
    if (threadIdx.x < Bsz) g_maxkey[threadIdx.x] = 0u;
}

// ---------------- 0) bf16 triple split ----------------
__global__ __launch_bounds__(256) void split_kernel(
    const float* __restrict__ x, const float* __restrict__ W1)
{
    int i = blockIdx.x * 256 + threadIdx.x;
    const int XTOT = M_TOT * FD;
    float v;
    __nv_bfloat16 *ph, *pm, *pl;
    int o;
    if (i < XTOT) {
        v = x[i]; ph = g_xh; pm = g_xm; pl = g_xl; o = i;
    } else {
        int k = i - XTOT;
        int j = k >> 10, f = k & 1023;
        v = W1[(j & 255) * 2048 + (j >> 8) * 1024 + f];
        ph = g_wh; pm = g_wm; pl = g_wl; o = k;
    }
    __nv_bfloat16 h = __float2bfloat16(v);
    float r1 = v - __bfloat162float(h);
    __nv_bfloat16 m = __float2bfloat16(r1);
    float r2 = r1 - __bfloat162float(m);
    ph[o] = h; pm[o] = m; pl[o] = __float2bfloat16(r2);
}

// ---------------- 1) mma.sync bf16 GEMM ----------------
// C[m][j] = sum_f x[m][f]*Bmat[j][f] (+b1 for j<256), via 6 split products.
// 128x64 CTA tile, 8 warps (4x2), each warp 32x32 (2 mtiles x 4 ntiles).
// KC=32 chunks, smem row stride 40 bf16 (20 words -> conflict-free frags).
#define MMA_BF16(d, a, b) \
    asm volatile("mma.sync.aligned.m16n8k16.row.col.f32.bf16.bf16.f32 " \
        "{%0,%1,%2,%3}, {%4,%5,%6,%7}, {%8,%9}, {%0,%1,%2,%3};" \
        : "+f"((d)[0]), "+f"((d)[1]), "+f"((d)[2]), "+f"((d)[3]) \
        : "r"((a)[0]), "r"((a)[1]), "r"((a)[2]), "r"((a)[3]), "r"((b)[0]), "r"((b)[1]))

__global__ __launch_bounds__(256) void mma_gemm_kernel(const float* __restrict__ b1)
{
    __shared__ __nv_bfloat16 smA[3][128][40];   // 30720 B
    __shared__ __nv_bfloat16 smB[3][64][40];    // 15360 B
    const int tid = threadIdx.x;
    const int j0 = blockIdx.x << 6;
    const int m0 = blockIdx.y << 7;
    const int wid = tid >> 5, lane = tid & 31;
    const int wr = wid >> 1, wc = wid & 1;
    const int g = lane >> 2, t = lane & 3;

    const __nv_bfloat16* xs[3] = {g_xh, g_xm, g_xl};
    const __nv_bfloat16* ws[3] = {g_wh, g_wm, g_wl};

    float acc[2][4][4] = {};
    uint4 pa[6], pb[3];

    // prefetch chunk 0
    #pragma unroll
    for (int u = 0; u < 6; u++) {
        int idx = tid + (u << 8);
        int s = idx >> 9, rem = idx & 511, row = rem >> 2, q = rem & 3;
        pa[u] = *(const uint4*)(xs[s] + (size_t)(m0 + row) * 1024 + q * 8);
    }
    #pragma unroll
    for (int u = 0; u < 3; u++) {
        int idx = tid + (u << 8);
        int s = idx >> 8, rem = idx & 255, row = rem >> 2, q = rem & 3;
        pb[u] = *(const uint4*)(ws[s] + (size_t)(j0 + row) * 1024 + q * 8);
    }

    for (int c = 0; c < 32; c++) {
        __syncthreads();
        #pragma unroll
        for (int u = 0; u < 6; u++) {
            int idx = tid + (u << 8);
            int s = idx >> 9, rem = idx & 511, row = rem >> 2, q = rem & 3;
            *(uint4*)&smA[s][row][q * 8] = pa[u];
        }
        #pragma unroll
        for (int u = 0; u < 3; u++) {
            int idx = tid + (u << 8);
            int s = idx >> 8, rem = idx & 255, row = rem >> 2, q = rem & 3;
            *(uint4*)&smB[s][row][q * 8] = pb[u];
        }
        __syncthreads();
        if (c < 31) {
            const int kc = (c + 1) << 5;
            #pragma unroll
            for (int u = 0; u < 6; u++) {
                int idx = tid + (u << 8);
                int s = idx >> 9, rem = idx & 511, row = rem >> 2, q = rem & 3;
                pa[u] = *(const uint4*)(xs[s] + (size_t)(m0 + row) * 1024 + kc + q * 8);
            }
            #pragma unroll
            for (int u = 0; u < 3; u++) {
                int idx = tid + (u << 8);
                int s = idx >> 8, rem = idx & 255, row = rem >> 2, q = rem & 3;
                pb[u] = *(const uint4*)(ws[s] + (size_t)(j0 + row) * 1024 + kc + q * 8);
            }
        }
        #pragma unroll
        for (int kk = 0; kk < 2; kk++) {
            const int w0 = kk * 8 + t;
            unsigned af[3][2][4], bf[3][4][2];
            #pragma unroll
            for (int s = 0; s < 3; s++) {
                #pragma unroll
                for (int mt = 0; mt < 2; mt++) {
                    const unsigned* r0 = (const unsigned*)&smA[s][wr * 32 + mt * 16 + g][0];
                    const unsigned* r1 = (const unsigned*)&smA[s][wr * 32 + mt * 16 + g + 8][0];
                    af[s][mt][0] = r0[w0];
                    af[s][mt][1] = r1[w0];
                    af[s][mt][2] = r0[w0 + 4];
                    af[s][mt][3] = r1[w0 + 4];
                }
                #pragma unroll
                for (int nt = 0; nt < 4; nt++) {
                    const unsigned* r0 = (const unsigned*)&smB[s][wc * 32 + nt * 8 + g][0];
                    bf[s][nt][0] = r0[w0];
                    bf[s][nt][1] = r0[w0 + 4];
                }
            }
            #pragma unroll
            for (int mt = 0; mt < 2; mt++)
                #pragma unroll
                for (int nt = 0; nt < 4; nt++) {
                    MMA_BF16(acc[mt][nt], af[0][mt], bf[0][nt]);   // h*h
                    MMA_BF16(acc[mt][nt], af[0][mt], bf[1][nt]);   // h*m
                    MMA_BF16(acc[mt][nt], af[1][mt], bf[0][nt]);   // m*h
                    MMA_BF16(acc[mt][nt], af[0][mt], bf[2][nt]);   // h*l
                    MMA_BF16(acc[mt][nt], af[2][mt], bf[0][nt]);   // l*h
                    MMA_BF16(acc[mt][nt], af[1][mt], bf[1][nt]);   // m*m
                }
        }
    }
    // epilogue: fold b1 into cols < 256, write g_pp
    #pragma unroll
    for (int nt = 0; nt < 4; nt++) {
        const int col = j0 + wc * 32 + nt * 8 + 2 * t;
        float b0 = (col < 256) ? b1[col] : 0.f;
        float b1v = (col < 256) ? b1[col + 1] : 0.f;
        #pragma unroll
        for (int mt = 0; mt < 2; mt++) {
            const int row = m0 + wr * 32 + mt * 16 + g;
            *(float2*)(g_pp + (size_t)row * 512 + col) =
                make_float2(acc[mt][nt][0] + b0, acc[mt][nt][1] + b1v);
            *(float2*)(g_pp + (size_t)(row + 8) * 512 + col) =
                make_float2(acc[mt][nt][2] + b0, acc[mt][nt][3] + b1v);
        }
    }
}

// ---------------- 2) edge (R1 verbatim) ----------------
__global__ __launch_bounds__(256) void edge_kernel(
    const float* __restrict__ W2, const float* __restrict__ b2, float* __restrict__ out_edge)
{
    __shared__ float prs[64][33];
    __shared__ float pcs[64][33];
    __shared__ float w2s[32];
    __shared__ float redbuf[8];
    const int b  = blockIdx.z;
    const int i0 = blockIdx.y << 6;
    const int j0 = blockIdx.x << 6;
    const int tid = threadIdx.x;
    const int tx = tid & 15, ty = tid >> 4;
    const float* base = g_pp + (b << 8) * 512;
    float acc[4][4] = {};
    for (int hc = 0; hc < 256; hc += 32) {
        __syncthreads();
        #pragma unroll
        for (int t = 0; t < 2; t++) {
            int idx = tid + (t << 8);
            int r = idx >> 3;
            int hv = (idx & 7) << 2;
            float4 v = *(const float4*)(base + (i0 + r) * 512 + hc + hv);
            prs[r][hv] = v.x; prs[r][hv + 1] = v.y; prs[r][hv + 2] = v.z; prs[r][hv + 3] = v.w;
            float4 u = *(const float4*)(base + (j0 + r) * 512 + 256 + hc + hv);
            pcs[r][hv] = u.x; pcs[r][hv + 1] = u.y; pcs[r][hv + 2] = u.z; pcs[r][hv + 3] = u.w;
        }
        if (tid < 32) w2s[tid] = W2[hc + tid];
        __syncthreads();
        #pragma unroll
        for (int h = 0; h < 32; h++) {
            float w = w2s[h];
            float a[4], c[4];
            #pragma unroll
            for (int t = 0; t < 4; t++) { a[t] = prs[(ty << 2) + t][h]; c[t] = pcs[(tx << 2) + t][h]; }
            #pragma unroll
            for (int i = 0; i < 4; i++)
                #pragma unroll
                for (int j = 0; j < 4; j++) {
                    float v = a[i] + c[j];
                    v = fmaxf(v, 0.f);
                    acc[i][j] = fmaf(v, w, acc[i][j]);
                }
        }
    }
    float bb = b2[0];
    float lmax = -3.4e38f;
    #pragma unroll
    for (int i = 0; i < 4; i++) {
        int ii = i0 + (ty << 2) + i;
        #pragma unroll
        for (int j = 0; j < 4; j++) {
            int jj = j0 + (tx << 2) + j;
            float e = acc[i][j] + bb;
            out_edge[(b << 16) + (ii << 8) + jj] = e;
            lmax = fmaxf(lmax, e);
        }
    }
    #pragma unroll
    for (int o = 16; o > 0; o >>= 1) lmax = fmaxf(lmax, __shfl_xor_sync(0xffffffffu, lmax, o));
    if ((tid & 31) == 0) redbuf[tid >> 5] = lmax;
    __syncthreads();
    if (tid == 0) {
        float m = redbuf[0];
        #pragma unroll
        for (int i = 1; i < 8; i++) m = fmaxf(m, redbuf[i]);
        atomicMax(&g_maxkey[b], encf(m));
    }
}

// ---------------- 3) exp + partial sums (R1 verbatim) ----------------
__global__ __launch_bounds__(256) void exp_kernel(const float* __restrict__ edge)
{
    const int b = blockIdx.y;
    const int blk = blockIdx.x;
    const int tid = threadIdx.x;
    __shared__ float red[8];
    const float smax = 2.0f * decf(g_maxkey[b]);
    const int base = (b << 16) + (blk << 10);
    float s = 0.f;
    #pragma unroll
    for (int t = 0; t < 4; t++) {
        int idx = base + (t << 8) + tid;
        float e2 = __expf(fmaf(edge[idx], 2.0f, -smax));
        g_e[idx] = e2;
        s += e2;
    }
    #pragma unroll
    for (int o = 16; o > 0; o >>= 1) s += __shfl_xor_sync(0xffffffffu, s, o);
    if ((tid & 31) == 0) red[tid >> 5] = s;
    __syncthreads();
    if (tid == 0) {
        float tot = 0.f;
        #pragma unroll
        for (int i = 0; i < 8; i++) tot += red[i];
        g_part[(b << 6) + blk] = tot;
    }
}

__global__ void denom_kernel() {
    const int b = blockIdx.x, tid = threadIdx.x;
    __shared__ float r2[2];
    float v = g_part[(b << 6) + tid];
    #pragma unroll
    for (int o = 16; o > 0; o >>= 1) v += __shfl_xor_sync(0xffffffffu, v, o);
    if ((tid & 31) == 0) r2[tid >> 5] = v;
    __syncthreads();
    if (tid == 0) g_inv_denom[b] = 1.0f / (r2[0] + r2[1]);
}

__global__ void soft_kernel(float* __restrict__ out_soft) {
    int idx = blockIdx.x * 256 + threadIdx.x;
    out_soft[idx] = g_e[idx] * g_inv_denom[idx >> 16];
}

// ---------------- 4) radix select (warp-aggregated, R4-verified) ----------------
__global__ __launch_bounds__(1024) void select_kernel(const float* __restrict__ soft)
{
    __shared__ unsigned hist[8][256];
    __shared__ unsigned sh_prefix;
    __shared__ int sh_rem;
    const int b = blockIdx.x;
    const int tid = threadIdx.x;
    const unsigned* keys = (const unsigned*)(soft + (b << 16));
    if (tid == 0) { sh_rem = Ksel; sh_prefix = 0u; }
    unsigned mask = 0u;
    for (int byte = 3; byte >= 0; byte--) {
        for (int i = tid; i < 2048; i += 1024) ((unsigned*)hist)[i] = 0u;
        __syncthreads();
        const unsigned prefix = sh_prefix;
        const int wg = (tid >> 5) & 7;
        const int sh = byte << 3;
        for (int t = tid; t < NN; t += 1024) {
            unsigned key = keys[t];
            bool act = (key & mask) == prefix;
            unsigned bucket = (key >> sh) & 255u;
            unsigned am = __ballot_sync(0xffffffffu, act);
            if (act) {
                unsigned peers = __match_any_sync(am, bucket);
                if ((unsigned)(__ffs(peers) - 1) == (tid & 31u))
                    atomicAdd(&hist[wg][bucket], __popc(peers));
            }
        }
        __syncthreads();
        if (tid < 256) {
            unsigned s = 0;
            #pragma unroll
            for (int c = 0; c < 8; c++) s += hist[c][tid];
            hist[0][tid] = s;
        }
        __syncthreads();
        if (tid == 0) {
            int rem = sh_rem;
            unsigned cum = 0;
            int sel = 0;
            for (int bb = 255; bb >= 0; bb--) {
                unsigned c = hist[0][bb];
                if (cum + c >= (unsigned)rem) { sel = bb; sh_rem = rem - (int)cum; break; }
                cum += c;
            }
            sh_prefix = prefix | ((unsigned)sel << sh);
        }
        __syncthreads();
        mask |= (255u << sh);
    }
    if (tid == 0) g_thr[b] = __uint_as_float(sh_prefix);
}

// ---------------- 5) masked sum + final (R1 verbatim) ----------------
__global__ __launch_bounds__(256) void cmask_sum_kernel(const float* __restrict__ soft)
{
    const int b = blockIdx.y, blk = blockIdx.x, tid = threadIdx.x;
    __shared__ float red[8];
    const float thr = g_thr[b];
    const int base = (b << 16) + (blk << 10);
    float s = 0.f;
    #pragma unroll
    for (int t = 0; t < 4; t++) {
        float v = soft[base + (t << 8) + tid];
        if (v >= thr) s += v;
    }
    #pragma unroll
    for (int o = 16; o > 0; o >>= 1) s += __shfl_xor_sync(0xffffffffu, s, o);
    if ((tid & 31) == 0) red[tid >> 5] = s;
    __syncthreads();
    if (tid == 0) {
        float tot = 0.f;
        #pragma unroll
        for (int i = 0; i < 8; i++) tot += red[i];
        g_cpart[(b << 6) + blk] = tot;
    }
}

__global__ void csum_final_kernel() {
    const int b = blockIdx.x, tid = threadIdx.x;
    __shared__ float r2[2];
    float v = g_cpart[(b << 6) + tid];
    #pragma unroll
    for (int o = 16; o > 0; o >>= 1) v += __shfl_xor_sync(0xffffffffu, v, o);
    if ((tid & 31) == 0) r2[tid >> 5] = v;
    __syncthreads();
    if (tid == 0) g_inv_csum[b] = 1.0f / (r2[0] + r2[1] + 1e-12f);
}

__global__ void final_kernel(const float* __restrict__ soft,
                             float* __restrict__ out_causal, float* __restrict__ out_conf)
{
    int idx = blockIdx.x * 256 + threadIdx.x;
    int b = idx >> 16;
    float v = soft[idx];
    float c = (v >= g_thr[b]) ? v * g_inv_csum[b] : 0.f;
    out_causal[idx] = c;
    out_conf[idx] = 1.f - c;
}

// ---------------- launch ----------------
extern "C" void kernel_launch(void* const* d_in, const int* in_sizes, int n_in,
                              void* d_out, int out_size)
{
    const float* x  = (const float*)d_in[0];
    const float* W1 = (const float*)d_in[1];
    const float* b1 = (const float*)d_in[2];
    const float* W2 = (const float*)d_in[3];
    const float* b2 = (const float*)d_in[4];
    float* out = (float*)d_out;
    float* out_causal = out;
    float* out_conf   = out + BNN;
    float* out_edge   = out + 2 * BNN;
    float* out_soft   = out + 3 * BNN;

    init_kernel<<<1, 32>>>();
    split_kernel<<<(M_TOT * FD + 512 * FD) / 256, 256>>>(x, W1);
    mma_gemm_kernel<<<dim3(8, 16), 256>>>(b1);
    edge_kernel<<<dim3(4, 4, Bsz), 256>>>(W2, b2, out_edge);
    exp_kernel<<<dim3(64, Bsz), 256>>>(out_edge);
    denom_kernel<<<Bsz, 64>>>();
    soft_kernel<<<2048, 256>>>(out_soft);
    select_kernel<<<Bsz, 1024>>>(out_soft);
    cmask_sum_kernel<<<dim3(64, Bsz), 256>>>(out_soft);
    csum_final_kernel<<<Bsz, 64>>>();
    final_kernel<<<2048, 256>>>(out_soft, out_causal, out_conf);
}

// round 10
// speedup vs baseline: 1.0929x; 1.0929x over previous
#include <cuda_runtime.h>

#define Bsz 8
#define FD 1024
#define NN 65536
#define BNN (Bsz*NN)
#define Ksel 39321
#define M_TOT 2048

// ---------------- scratch ----------------
__device__ float    g_pp[M_TOT * 512];     // [m][0:256)=pr+b1, [256:512)=pc
__device__ float    g_e[BNN];
__device__ unsigned g_maxkey[Bsz];
__device__ float    g_inv_denom[Bsz];
__device__ float    g_part[Bsz * 64];
__device__ float    g_thr[Bsz];
__device__ float    g_cpart[Bsz * 64];
__device__ float    g_inv_csum[Bsz];

// monotone float<->uint encoding
__device__ __forceinline__ unsigned encf(float f) {
    unsigned u = __float_as_uint(f);
    return (u & 0x80000000u) ? ~u : (u | 0x80000000u);
}
__device__ __forceinline__ float decf(unsigned u) {
    unsigned v = (u & 0x80000000u) ? (u ^ 0x80000000u) : ~u;
    return __uint_as_float(v);
}

__global__ void init_kernel() {
    if (threadIdx.x < Bsz) g_maxkey[threadIdx.x] = 0u;
}

// ---------------- 1) GEMM: C[m][j] = sum_f x[m][f]*Bmat[j][f] ----------------
// 64x64 tile, 256 threads, 4x4/thread, 256 CTAs, double-buffered smem,
// ONE __syncthreads per 16-k chunk.
__global__ __launch_bounds__(256) void gemm_kernel(
    const float* __restrict__ x, const float* __restrict__ W1, const float* __restrict__ b1)
{
    __shared__ float As[2][16][68];
    __shared__ float Bs[2][16][68];
    const int tid = threadIdx.x;
    const int j0 = blockIdx.x << 6;
    const int m0 = blockIdx.y << 6;
    const int tx = tid & 15, ty = tid >> 4;
    const int ar = tid >> 2;            // 0..63
    const int ac4 = (tid & 3) << 2;     // 0,4,8,12
    const int gj = j0 + ar;
    const float* wrow = W1 + (gj & 255) * 2048 + (gj >> 8) * 1024 + ac4;
    const float* arow = x + (m0 + ar) * 1024 + ac4;

    float acc[4][4] = {};

    float4 pa = *(const float4*)(arow);
    float4 pb = *(const float4*)(wrow);
    {
        float va[4] = {pa.x, pa.y, pa.z, pa.w};
        float vb[4] = {pb.x, pb.y, pb.z, pb.w};
        #pragma unroll
        for (int d = 0; d < 4; d++) { As[0][ac4 + d][ar] = va[d]; Bs[0][ac4 + d][ar] = vb[d]; }
    }
    __syncthreads();

    for (int c = 0; c < 64; c++) {
        const int cur = c & 1;
        if (c < 63) {
            pa = *(const float4*)(arow + (c + 1) * 16);
            pb = *(const float4*)(wrow + (c + 1) * 16);
        }
        #pragma unroll
        for (int k = 0; k < 16; k++) {
            float a[4], bb[4];
            *(float4*)a  = *(const float4*)&As[cur][k][ty << 2];
            *(float4*)bb = *(const float4*)&Bs[cur][k][tx << 2];
            #pragma unroll
            for (int i = 0; i < 4; i++)
                #pragma unroll
                for (int j = 0; j < 4; j++)
                    acc[i][j] = fmaf(a[i], bb[j], acc[i][j]);
        }
        if (c < 63) {
            const int nxt = cur ^ 1;
            float va[4] = {pa.x, pa.y, pa.z, pa.w};
            float vb[4] = {pb.x, pb.y, pb.z, pb.w};
            #pragma unroll
            for (int d = 0; d < 4; d++) { As[nxt][ac4 + d][ar] = va[d]; Bs[nxt][ac4 + d][ar] = vb[d]; }
            __syncthreads();
        }
    }
    float bias[4];
    #pragma unroll
    for (int jj = 0; jj < 4; jj++) {
        int col = j0 + (tx << 2) + jj;
        bias[jj] = (col < 256) ? b1[col] : 0.f;
    }
    #pragma unroll
    for (int i = 0; i < 4; i++) {
        int m = m0 + (ty << 2) + i;
        *(float4*)(g_pp + m * 512 + j0 + (tx << 2)) =
            make_float4(acc[i][0] + bias[0], acc[i][1] + bias[1],
                        acc[i][2] + bias[2], acc[i][3] + bias[3]);
    }
}

// ---------------- 2) edge: 32x64 tile, 256 CTAs, transposed smem ----------------
__global__ __launch_bounds__(256) void edge_kernel(
    const float* __restrict__ W2, const float* __restrict__ b2, float* __restrict__ out_edge)
{
    __shared__ float prsT[32][36];   // [h][i], 16B-aligned rows for LDS.128 broadcast
    __shared__ float pcsT[32][66];   // [h][j], 8B-aligned rows for LDS.64
    __shared__ float w2s[32];
    __shared__ float redbuf[8];
    const int b  = blockIdx.z;
    const int i0 = blockIdx.y << 5;       // 8 i-blocks
    const int j0 = blockIdx.x << 6;       // 4 j-blocks
    const int tid = threadIdx.x;
    const int tx = tid & 31;              // j cols 2tx, 2tx+1
    const int ty = tid >> 5;              // i rows 4ty..4ty+3
    const float* base = g_pp + (b << 8) * 512;
    float acc[4][2] = {};
    for (int hc = 0; hc < 256; hc += 32) {
        __syncthreads();
        {
            int r = tid >> 3, hv = (tid & 7) << 2;
            float4 v = *(const float4*)(base + (i0 + r) * 512 + hc + hv);
            prsT[hv + 0][r] = v.x; prsT[hv + 1][r] = v.y;
            prsT[hv + 2][r] = v.z; prsT[hv + 3][r] = v.w;
            #pragma unroll
            for (int t = 0; t < 2; t++) {
                int idx = tid + (t << 8);
                int rr = idx >> 3, hh = (idx & 7) << 2;
                float4 u = *(const float4*)(base + (j0 + rr) * 512 + 256 + hc + hh);
                pcsT[hh + 0][rr] = u.x; pcsT[hh + 1][rr] = u.y;
                pcsT[hh + 2][rr] = u.z; pcsT[hh + 3][rr] = u.w;
            }
        }
        if (tid < 32) w2s[tid] = W2[hc + tid];
        __syncthreads();
        #pragma unroll
        for (int h = 0; h < 32; h++) {
            float w = w2s[h];
            float4 a4 = *(const float4*)&prsT[h][ty << 2];
            float2 c2 = *(const float2*)&pcsT[h][tx << 1];
            float a[4] = {a4.x, a4.y, a4.z, a4.w};
            #pragma unroll
            for (int i = 0; i < 4; i++) {
                acc[i][0] = fmaf(fmaxf(a[i] + c2.x, 0.f), w, acc[i][0]);
                acc[i][1] = fmaf(fmaxf(a[i] + c2.y, 0.f), w, acc[i][1]);
            }
        }
    }
    float bb = b2[0];
    float lmax = -3.4e38f;
    #pragma unroll
    for (int i = 0; i < 4; i++) {
        float e0 = acc[i][0] + bb;
        float e1 = acc[i][1] + bb;
        *(float2*)(out_edge + (b << 16) + ((i0 + (ty << 2) + i) << 8) + j0 + (tx << 1)) =
            make_float2(e0, e1);
        lmax = fmaxf(lmax, fmaxf(e0, e1));
    }
    #pragma unroll
    for (int o = 16; o > 0; o >>= 1) lmax = fmaxf(lmax, __shfl_xor_sync(0xffffffffu, lmax, o));
    if ((tid & 31) == 0) redbuf[tid >> 5] = lmax;
    __syncthreads();
    if (tid == 0) {
        float m = redbuf[0];
        #pragma unroll
        for (int i = 1; i < 8; i++) m = fmaxf(m, redbuf[i]);
        atomicMax(&g_maxkey[b], encf(m));
    }
}

// ---------------- 3) exp + partial sums (R1 verbatim) ----------------
__global__ __launch_bounds__(256) void exp_kernel(const float* __restrict__ edge)
{
    const int b = blockIdx.y;
    const int blk = blockIdx.x;
    const int tid = threadIdx.x;
    __shared__ float red[8];
    const float smax = 2.0f * decf(g_maxkey[b]);
    const int base = (b << 16) + (blk << 10);
    float s = 0.f;
    #pragma unroll
    for (int t = 0; t < 4; t++) {
        int idx = base + (t << 8) + tid;
        float e2 = __expf(fmaf(edge[idx], 2.0f, -smax));
        g_e[idx] = e2;
        s += e2;
    }
    #pragma unroll
    for (int o = 16; o > 0; o >>= 1) s += __shfl_xor_sync(0xffffffffu, s, o);
    if ((tid & 31) == 0) red[tid >> 5] = s;
    __syncthreads();
    if (tid == 0) {
        float tot = 0.f;
        #pragma unroll
        for (int i = 0; i < 8; i++) tot += red[i];
        g_part[(b << 6) + blk] = tot;
    }
}

__global__ void denom_kernel() {
    const int b = blockIdx.x, tid = threadIdx.x;
    __shared__ float r2[2];
    float v = g_part[(b << 6) + tid];
    #pragma unroll
    for (int o = 16; o > 0; o >>= 1) v += __shfl_xor_sync(0xffffffffu, v, o);
    if ((tid & 31) == 0) r2[tid >> 5] = v;
    __syncthreads();
    if (tid == 0) g_inv_denom[b] = 1.0f / (r2[0] + r2[1]);
}

__global__ void soft_kernel(float* __restrict__ out_soft) {
    int idx = blockIdx.x * 256 + threadIdx.x;
    out_soft[idx] = g_e[idx] * g_inv_denom[idx >> 16];
}

// ---------------- 4) radix select: MLP-8 batched loads + warp-aggregated atomics ----------------
__global__ __launch_bounds__(1024) void select_kernel(const float* __restrict__ soft)
{
    __shared__ unsigned hist[8][256];
    __shared__ unsigned sh_prefix;
    __shared__ int sh_rem;
    const int b = blockIdx.x;
    const int tid = threadIdx.x;
    const unsigned* keys = (const unsigned*)(soft + (b << 16));
    if (tid == 0) { sh_rem = Ksel; sh_prefix = 0u; }
    unsigned mask = 0u;
    for (int byte = 3; byte >= 0; byte--) {
        for (int i = tid; i < 2048; i += 1024) ((unsigned*)hist)[i] = 0u;
        __syncthreads();
        const unsigned prefix = sh_prefix;
        const int wg = (tid >> 5) & 7;
        const int sh = byte << 3;
        for (int t0 = tid; t0 < NN; t0 += 8192) {     // 8 outer iters
            unsigned k[8];
            #pragma unroll
            for (int u = 0; u < 8; u++) k[u] = keys[t0 + u * 1024];
            #pragma unroll
            for (int u = 0; u < 8; u++) {
                bool act = (k[u] & mask) == prefix;
                unsigned bucket = (k[u] >> sh) & 255u;
                unsigned am = __ballot_sync(0xffffffffu, act);
                if (act) {
                    unsigned peers = __match_any_sync(am, bucket);
                    if ((unsigned)(__ffs(peers) - 1) == (tid & 31u))
                        atomicAdd(&hist[wg][bucket], __popc(peers));
                }
            }
        }
        __syncthreads();
        if (tid < 256) {
            unsigned s = 0;
            #pragma unroll
            for (int c = 0; c < 8; c++) s += hist[c][tid];
            hist[0][tid] = s;
        }
        __syncthreads();
        if (tid == 0) {
            int rem = sh_rem;
            unsigned cum = 0;
            int sel = 0;
            for (int bb = 255; bb >= 0; bb--) {
                unsigned c = hist[0][bb];
                if (cum + c >= (unsigned)rem) { sel = bb; sh_rem = rem - (int)cum; break; }
                cum += c;
            }
            sh_prefix = prefix | ((unsigned)sel << sh);
        }
        __syncthreads();
        mask |= (255u << sh);
    }
    if (tid == 0) g_thr[b] = __uint_as_float(sh_prefix);
}

// ---------------- 5) masked sum + final (R1 verbatim) ----------------
__global__ __launch_bounds__(256) void cmask_sum_kernel(const float* __restrict__ soft)
{
    const int b = blockIdx.y, blk = blockIdx.x, tid = threadIdx.x;
    __shared__ float red[8];
    const float thr = g_thr[b];
    const int base = (b << 16) + (blk << 10);
    float s = 0.f;
    #pragma unroll
    for (int t = 0; t < 4; t++) {
        float v = soft[base + (t << 8) + tid];
        if (v >= thr) s += v;
    }
    #pragma unroll
    for (int o = 16; o > 0; o >>= 1) s += __shfl_xor_sync(0xffffffffu, s, o);
    if ((tid & 31) == 0) red[tid >> 5] = s;
    __syncthreads();
    if (tid == 0) {
        float tot = 0.f;
        #pragma unroll
        for (int i = 0; i < 8; i++) tot += red[i];
        g_cpart[(b << 6) + blk] = tot;
    }
}

__global__ void csum_final_kernel() {
    const int b = blockIdx.x, tid = threadIdx.x;
    __shared__ float r2[2];
    float v = g_cpart[(b << 6) + tid];
    #pragma unroll
    for (int o = 16; o > 0; o >>= 1) v += __shfl_xor_sync(0xffffffffu, v, o);
    if ((tid & 31) == 0) r2[tid >> 5] = v;
    __syncthreads();
    if (tid == 0) g_inv_csum[b] = 1.0f / (r2[0] + r2[1] + 1e-12f);
}

__global__ void final_kernel(const float* __restrict__ soft,
                             float* __restrict__ out_causal, float* __restrict__ out_conf)
{
    int idx = blockIdx.x * 256 + threadIdx.x;
    int b = idx >> 16;
    float v = soft[idx];
    float c = (v >= g_thr[b]) ? v * g_inv_csum[b] : 0.f;
    out_causal[idx] = c;
    out_conf[idx] = 1.f - c;
}

// ---------------- launch ----------------
extern "C" void kernel_launch(void* const* d_in, const int* in_sizes, int n_in,
                              void* d_out, int out_size)
{
    const float* x  = (const float*)d_in[0];
    const float* W1 = (const float*)d_in[1];
    const float* b1 = (const float*)d_in[2];
    const float* W2 = (const float*)d_in[3];
    const float* b2 = (const float*)d_in[4];
    float* out = (float*)d_out;
    float* out_causal = out;
    float* out_conf   = out + BNN;
    float* out_edge   = out + 2 * BNN;
    float* out_soft   = out + 3 * BNN;

    init_kernel<<<1, 32>>>();
    gemm_kernel<<<dim3(8, 32), 256>>>(x, W1, b1);
    edge_kernel<<<dim3(4, 8, Bsz), 256>>>(W2, b2, out_edge);
    exp_kernel<<<dim3(64, Bsz), 256>>>(out_edge);
    denom_kernel<<<Bsz, 64>>>();
    soft_kernel<<<2048, 256>>>(out_soft);
    select_kernel<<<Bsz, 1024>>>(out_soft);
    cmask_sum_kernel<<<dim3(64, Bsz), 256>>>(out_soft);
    csum_final_kernel<<<Bsz, 64>>>();
    final_kernel<<<2048, 256>>>(out_soft, out_causal, out_conf);
}